// round 13
// baseline (speedup 1.0000x reference)
#include <cuda_runtime.h>
#include <cuda_fp16.h>
#include <stdint.h>

#define TS_X 32
#define TS_Y 8
#define ROWS_PER_T 4               // output rows per thread (per fp16 lane)
#define HALF_H (TS_Y * ROWS_PER_T) // 32
#define TILE_H (2 * HALF_H)        // 64 output rows per block (2 fp16 lanes)
#define PAD 3
#define SW (TS_X + 2*PAD)          // 38
#define SH (HALF_H + 2*PAD)        // 38
#define IMG_W 512
#define IMG_H 512

__constant__ float c_mean[3] = {0.485f, 0.456f, 0.406f};
__constant__ float c_std[3]  = {0.229f, 0.224f, 0.225f};

// ---------------- compile-time network generation ----------------
struct Op { unsigned char k, a, b; };   // k=0: CE(buf[a],buf[b]); k=1: buf[b]=buf[a]
struct IL { unsigned char v[44]; int n; };
struct Frag { Op ops[192]; int n; };
struct Prog { Op ops[900]; int n; unsigned char med[4]; };

__host__ __device__ static constexpr IL make_row(int r) {
    IL x{}; for (int c = 0; c < 7; ++c) x.v[x.n++] = (unsigned char)(r * 7 + c);
    return x;
}

__host__ __device__ static constexpr void zipF(Frag& D, const Frag& A, const Frag& B) {
    int i = 0, j = 0;
    while (i < A.n || j < B.n) {
        if (i < A.n) D.ops[D.n++] = A.ops[i++];
        if (j < B.n) D.ops[D.n++] = B.ops[j++];
    }
}

__host__ __device__ static constexpr void appendF(Prog& P, const Frag& F) {
    for (int i = 0; i < F.n; ++i) P.ops[P.n++] = F.ops[i];
}

// Batcher odd-even merge; children (even/odd sub-merges act on DISJOINT slots)
// are emitted into separate fragments and zipped for ILP. Comparator set is
// identical to sequential emission; only the order of independent ops differs.
__host__ __device__ static constexpr IL oem(const IL A, const IL B, Frag& P) {
    if (A.n == 0) return B;
    if (B.n == 0) return A;
    IL R{};
    if (A.n == 1 && B.n == 1) {
        P.ops[P.n++] = {0, A.v[0], B.v[0]};
        R.v[0] = A.v[0]; R.v[1] = B.v[0]; R.n = 2; return R;
    }
    IL Ae{}, Ao{}, Be{}, Bo{};
    for (int i = 0; i < A.n; ++i) { if (i % 2 == 0) Ae.v[Ae.n++] = A.v[i]; else Ao.v[Ao.n++] = A.v[i]; }
    for (int i = 0; i < B.n; ++i) { if (i % 2 == 0) Be.v[Be.n++] = B.v[i]; else Bo.v[Bo.n++] = B.v[i]; }
    Frag Pe{}, Po{};
    IL E = oem(Ae, Be, Pe);
    IL O = oem(Ao, Bo, Po);
    zipF(P, Pe, Po);
    R.v[R.n++] = E.v[0];
    int i = 1, j = 0;
    while (i < E.n && j < O.n) {
        P.ops[P.n++] = {0, O.v[j], E.v[i]};     // min -> O slot, max -> E slot
        R.v[R.n++] = O.v[j]; R.v[R.n++] = E.v[i];
        ++i; ++j;
    }
    while (j < O.n) R.v[R.n++] = O.v[j++];
    while (i < E.n) R.v[R.n++] = E.v[i++];
    return R;
}

__host__ __device__ static constexpr IL sort_gen(const IL A, Frag& P) {
    if (A.n <= 1) return A;
    IL L{}, R{};
    const int m = A.n / 2;
    for (int i = 0; i < m;   ++i) L.v[L.n++] = A.v[i];
    for (int i = m; i < A.n; ++i) R.v[R.n++] = A.v[i];
    Frag Pl{}, Pr{};
    IL Ls = sort_gen(L, Pl), Rs = sort_gen(R, Pr);
    zipF(P, Pl, Pr);
    return oem(Ls, Rs, P);
}

__host__ __device__ static constexpr IL copy_gen(const IL A, int dst0, Frag& P) {
    IL R{};
    for (int i = 0; i < A.n; ++i) {
        P.ops[P.n++] = {1, A.v[i], (unsigned char)(dst0 + i)};
        R.v[R.n++] = (unsigned char)(dst0 + i);
    }
    return R;
}

__host__ __device__ static constexpr IL sub(const IL A, int lo, int cnt) {
    IL R{}; for (int i = 0; i < cnt; ++i) R.v[R.n++] = A.v[lo + i]; return R;
}

// Same DAG as R11 (pair2 before pair1 for liveness), but independent
// modules adjacent in the schedule are zipped for ILP.
__host__ __device__ static constexpr Prog build() {
    Prog P{};
    // stage 1: rows 3,4 (+Bb) zipped with rows 5,6 (+Bc)
    Frag fa{}, fb{}, s1{};
    IL L3 = sort_gen(make_row(3), fa);
    IL L4 = sort_gen(make_row(4), fa);
    IL Bb = oem(L3, L4, fa);
    IL L5 = sort_gen(make_row(5), fb);
    IL L6 = sort_gen(make_row(6), fb);
    IL Bc = oem(L5, L6, fb);
    zipF(s1, fa, fb); appendF(P, s1);
    // stage 2: M (internally zipped) + preserved copy
    Frag s2{};
    IL M  = oem(Bb, Bc, s2);
    IL Mc = copy_gen(M, 84, s2);
    appendF(P, s2);
    // stage 3: rows 7,8 sorts zipped; preserve row7; Bd
    Frag f7{}, f8{}, s3{};
    IL L7 = sort_gen(make_row(7), f7);
    IL L8 = sort_gen(make_row(8), f8);
    zipF(s3, f7, f8);
    IL c7 = copy_gen(L7, 77, s3);
    IL Bd = oem(L7, L8, s3);
    appendF(P, s3);
    // stage 4: F2 = sorted 42 for pair 2
    Frag s4{};
    IL F2 = oem(M, Bd, s4);
    appendF(P, s4);
    IL m2 = sub(F2, 16, 10);            // ranks 17..26: only possible medians
    // stage 5: m2 copies + row9 sort, zipped with row2 sort + copy
    Frag f5a{}, f5b{}, s5{};
    IL m2c = copy_gen(m2, 112, f5a);
    IL L9  = sort_gen(make_row(9), f5a);
    IL L2  = sort_gen(make_row(2), f5b);
    IL c2  = copy_gen(L2, 70, f5b);
    zipF(s5, f5a, f5b); appendF(P, s5);
    // stage 6: G2 and G3 zipped (independent)
    Frag g2{}, g3{}, s6{};
    IL G2 = oem(m2,  c2, g2);
    IL G3 = oem(m2c, L9, g3);
    zipF(s6, g2, g3); appendF(P, s6);
    P.med[2] = G2.v[8];                 // rank 25 of 49 = rank 9 of 17
    P.med[3] = G3.v[8];
    // stage 7: row1 sort + Ba, zipped with row0 sort
    Frag f7a{}, f7b{}, s7{};
    IL L1 = sort_gen(make_row(1), f7a);
    IL Ba = oem(L1, L2, f7a);           // uses original (still sorted) L2 slots
    IL L0 = sort_gen(make_row(0), f7b);
    zipF(s7, f7a, f7b); appendF(P, s7);
    // stage 8: F1 = sorted 42 for pair 1
    Frag s8{};
    IL F1 = oem(Mc, Ba, s8);
    appendF(P, s8);
    IL m1 = sub(F1, 16, 10);
    // stage 9: m1 copies
    Frag s9{};
    IL m1c = copy_gen(m1, 122, s9);
    appendF(P, s9);
    // stage 10: G0 and G1 zipped (independent)
    Frag g0{}, g1{}, s10{};
    IL G0 = oem(m1,  L0, g0);
    IL G1 = oem(m1c, c7, g1);
    zipF(s10, g0, g1); appendF(P, s10);
    P.med[0] = G0.v[8];
    P.med[1] = G1.v[8];
    return P;
}

// ---------------- kernel ----------------
__device__ __forceinline__ void s2(__half2& a, __half2& b) {
    __half2 mn = __hmin2(a, b);
    b = __hmax2(a, b);
    a = mn;
}

__device__ __forceinline__ int reflect(int v, int n) {
    v = v < 0 ? -v : v;
    return v >= n ? 2 * (n - 1) - v : v;
}

__global__ __launch_bounds__(TS_X * TS_Y, 4) void median7_kernel(
    const float* __restrict__ in, float* __restrict__ out)
{
    // Compile-time evaluated; all indices below are literals after unroll,
    // so the whole network folds to straight-line register code.
    constexpr Prog PROG = build();

    __shared__ __half2 tile[SH][SW];

    const int z = blockIdx.z;
    const int c = z % 3;
    const float* img = in + (size_t)z * (IMG_W * IMG_H);
    float* o = out + (size_t)z * (IMG_W * IMG_H);

    const int tx0 = blockIdx.x * TS_X;
    const int ty0 = blockIdx.y * TILE_H;
    const int tid = threadIdx.y * TS_X + threadIdx.x;

    #pragma unroll
    for (int i = tid; i < SW * SH; i += TS_X * TS_Y) {
        const int r = i / SW, lxx = i % SW;
        const int gx  = reflect(tx0 + lxx - PAD, IMG_W);
        const int gyA = reflect(ty0 + r - PAD, IMG_H);
        const int gyB = reflect(ty0 + HALF_H + r - PAD, IMG_H);
        tile[r][lxx] = __floats2half2_rn(img[gyA * IMG_W + gx], img[gyB * IMG_W + gx]);
    }
    __syncthreads();

    const int lx = threadIdx.x;
    const int wy = ROWS_PER_T * threadIdx.y;   // first output row (tile row offset)

    __half2 buf[132];
    #pragma unroll
    for (int r = 0; r < 10; ++r)
        #pragma unroll
        for (int cc = 0; cc < 7; ++cc)
            buf[r * 7 + cc] = tile[wy + r][lx + cc];

    #pragma unroll
    for (int k = 0; k < PROG.n; ++k) {
        if (PROG.ops[k].k == 0) s2(buf[PROG.ops[k].a], buf[PROG.ops[k].b]);
        else                    buf[PROG.ops[k].b] = buf[PROG.ops[k].a];
    }

    const float mu = c_mean[c], sd = c_std[c];
    const float inv_sd = 1.0f / sd;
    const int gx = tx0 + lx;

    #pragma unroll
    for (int px = 0; px < ROWS_PER_T; ++px) {
        const __half2 med2 = buf[PROG.med[px]];
        const float medA = __low2float(med2);
        const float medB = __high2float(med2);

        float uA = fmaf(medA, sd, mu);
        uA = fminf(fmaxf(uA, 0.0f), 1.0f);
        o[(ty0 + wy + px) * IMG_W + gx] = (uA - mu) * inv_sd;

        float uB = fmaf(medB, sd, mu);
        uB = fminf(fmaxf(uB, 0.0f), 1.0f);
        o[(ty0 + HALF_H + wy + px) * IMG_W + gx] = (uB - mu) * inv_sd;
    }
}

extern "C" void kernel_launch(void* const* d_in, const int* in_sizes, int n_in,
                              void* d_out, int out_size)
{
    const float* image = (const float*)d_in[0];
    const float* mask  = (const float*)d_in[1];
    float* out = (float*)d_out;

    const int img_elems  = in_sizes[0];
    const int mask_elems = in_sizes[1];
    const int planes = img_elems / (IMG_W * IMG_H);

    dim3 block(TS_X, TS_Y);
    dim3 grid(IMG_W / TS_X, IMG_H / TILE_H, planes);
    median7_kernel<<<grid, block>>>(image, out);

    cudaMemcpyAsync(out + img_elems, mask,
                    (size_t)mask_elems * sizeof(float),
                    cudaMemcpyDeviceToDevice, 0);
}

// round 14
// speedup vs baseline: 1.5579x; 1.5579x over previous
#include <cuda_runtime.h>
#include <cuda_fp16.h>
#include <stdint.h>

#define TS_X 32
#define TS_Y 8
#define ROWS_PER_T 4               // output rows per thread (per fp16 lane)
#define HALF_H (TS_Y * ROWS_PER_T) // 32
#define TILE_H (2 * HALF_H)        // 64 output rows per block (2 fp16 lanes)
#define PAD 3
#define SW (TS_X + 2*PAD)          // 38
#define SH (HALF_H + 2*PAD)        // 38
#define IMG_W 512
#define IMG_H 512

__constant__ float c_mean[3] = {0.485f, 0.456f, 0.406f};
__constant__ float c_std[3]  = {0.229f, 0.224f, 0.225f};

// ---------------- compile-time network generation ----------------
struct Op { unsigned char k, a, b; };   // k=0: CE(buf[a],buf[b]); k=1: buf[b]=buf[a]
struct IL { unsigned char v[44]; int n; };
struct Frag { Op ops[192]; int n; };
struct Prog { Op ops[900]; int n; unsigned char med[4]; };

__host__ __device__ static constexpr IL make_row(int r) {
    IL x{}; for (int c = 0; c < 7; ++c) x.v[x.n++] = (unsigned char)(r * 7 + c);
    return x;
}

__host__ __device__ static constexpr void zipF(Frag& D, const Frag& A, const Frag& B) {
    int i = 0, j = 0;
    while (i < A.n || j < B.n) {
        if (i < A.n) D.ops[D.n++] = A.ops[i++];
        if (j < B.n) D.ops[D.n++] = B.ops[j++];
    }
}

__host__ __device__ static constexpr void appendF(Prog& P, const Frag& F) {
    for (int i = 0; i < F.n; ++i) P.ops[P.n++] = F.ops[i];
}

// Batcher odd-even merge. The even/odd sub-merges act on DISJOINT slots that
// are all live at merge entry, so zipping them is liveness-neutral ILP.
__host__ __device__ static constexpr IL oem(const IL A, const IL B, Frag& P) {
    if (A.n == 0) return B;
    if (B.n == 0) return A;
    IL R{};
    if (A.n == 1 && B.n == 1) {
        P.ops[P.n++] = {0, A.v[0], B.v[0]};
        R.v[0] = A.v[0]; R.v[1] = B.v[0]; R.n = 2; return R;
    }
    IL Ae{}, Ao{}, Be{}, Bo{};
    for (int i = 0; i < A.n; ++i) { if (i % 2 == 0) Ae.v[Ae.n++] = A.v[i]; else Ao.v[Ao.n++] = A.v[i]; }
    for (int i = 0; i < B.n; ++i) { if (i % 2 == 0) Be.v[Be.n++] = B.v[i]; else Bo.v[Bo.n++] = B.v[i]; }
    Frag Pe{}, Po{};
    IL E = oem(Ae, Be, Pe);
    IL O = oem(Ao, Bo, Po);
    zipF(P, Pe, Po);
    R.v[R.n++] = E.v[0];
    int i = 1, j = 0;
    while (i < E.n && j < O.n) {
        P.ops[P.n++] = {0, O.v[j], E.v[i]};     // min -> O slot, max -> E slot
        R.v[R.n++] = O.v[j]; R.v[R.n++] = E.v[i];
        ++i; ++j;
    }
    while (j < O.n) R.v[R.n++] = O.v[j++];
    while (i < E.n) R.v[R.n++] = E.v[i++];
    return R;
}

// The two halves are disjoint and live from entry: zip is liveness-neutral.
__host__ __device__ static constexpr IL sort_gen(const IL A, Frag& P) {
    if (A.n <= 1) return A;
    IL L{}, R{};
    const int m = A.n / 2;
    for (int i = 0; i < m;   ++i) L.v[L.n++] = A.v[i];
    for (int i = m; i < A.n; ++i) R.v[R.n++] = A.v[i];
    Frag Pl{}, Pr{};
    IL Ls = sort_gen(L, Pl), Rs = sort_gen(R, Pr);
    zipF(P, Pl, Pr);
    return oem(Ls, Rs, P);
}

__host__ __device__ static constexpr IL copy_gen(const IL A, int dst0, Frag& P) {
    IL R{};
    for (int i = 0; i < A.n; ++i) {
        P.ops[P.n++] = {1, A.v[i], (unsigned char)(dst0 + i)};
        R.v[R.n++] = (unsigned char)(dst0 + i);
    }
    return R;
}

__host__ __device__ static constexpr IL sub(const IL A, int lo, int cnt) {
    IL R{}; for (int i = 0; i < cnt; ++i) R.v[R.n++] = A.v[lo + i]; return R;
}

// R11's strictly-sequential module order (lifetime-disjoint modules, pair2
// fully before pair1). The ONLY change vs R11: recursive intra-merge zip.
__host__ __device__ static constexpr Prog build() {
    Prog P{};
    { Frag f{}; IL L3 = sort_gen(make_row(3), f); IL L4 = sort_gen(make_row(4), f);
      IL Bb = oem(L3, L4, f);
      Frag g{}; IL L5 = sort_gen(make_row(5), g); IL L6 = sort_gen(make_row(6), g);
      IL Bc = oem(L5, L6, g);
      appendF(P, f); appendF(P, g);
      Frag h{}; IL M = oem(Bb, Bc, h); IL Mc = copy_gen(M, 84, h); appendF(P, h);
      // ---- pair 2 ----
      Frag i1{}; IL L7 = sort_gen(make_row(7), i1); IL c7 = copy_gen(L7, 77, i1);
      IL L8 = sort_gen(make_row(8), i1); IL Bd = oem(L7, L8, i1); appendF(P, i1);
      Frag i2{}; IL F2 = oem(M, Bd, i2); appendF(P, i2);
      IL m2 = sub(F2, 16, 10);          // ranks 17..26: only possible medians
      Frag i3{}; IL m2c = copy_gen(m2, 112, i3);
      IL L2 = sort_gen(make_row(2), i3); IL c2 = copy_gen(L2, 70, i3); appendF(P, i3);
      Frag i4{}; IL G2 = oem(m2, c2, i4); appendF(P, i4);
      P.med[2] = G2.v[8];               // rank 25 of 49 = rank 9 of 17
      Frag i5{}; IL L9 = sort_gen(make_row(9), i5);
      IL G3 = oem(m2c, L9, i5); appendF(P, i5);
      P.med[3] = G3.v[8];
      // ---- pair 1 ----
      Frag j1{}; IL L1 = sort_gen(make_row(1), j1);
      IL Ba = oem(L1, L2, j1); appendF(P, j1);   // original L2 slots still sorted
      Frag j2{}; IL F1 = oem(Mc, Ba, j2); appendF(P, j2);
      IL m1 = sub(F1, 16, 10);
      Frag j3{}; IL m1c = copy_gen(m1, 122, j3);
      IL L0 = sort_gen(make_row(0), j3); appendF(P, j3);
      Frag j4{}; IL G0 = oem(m1, L0, j4); appendF(P, j4);
      P.med[0] = G0.v[8];
      Frag j5{}; IL G1 = oem(m1c, c7, j5); appendF(P, j5);
      P.med[1] = G1.v[8];
    }
    return P;
}

// ---------------- kernel ----------------
__device__ __forceinline__ void s2(__half2& a, __half2& b) {
    __half2 mn = __hmin2(a, b);
    b = __hmax2(a, b);
    a = mn;
}

__device__ __forceinline__ int reflect(int v, int n) {
    v = v < 0 ? -v : v;
    return v >= n ? 2 * (n - 1) - v : v;
}

__global__ __launch_bounds__(TS_X * TS_Y, 4) void median7_kernel(
    const float* __restrict__ in, float* __restrict__ out)
{
    // Compile-time evaluated; all indices below are literals after unroll,
    // so the whole network folds to straight-line register code.
    constexpr Prog PROG = build();

    __shared__ __half2 tile[SH][SW];

    const int z = blockIdx.z;
    const int c = z % 3;
    const float* img = in + (size_t)z * (IMG_W * IMG_H);
    float* o = out + (size_t)z * (IMG_W * IMG_H);

    const int tx0 = blockIdx.x * TS_X;
    const int ty0 = blockIdx.y * TILE_H;
    const int tid = threadIdx.y * TS_X + threadIdx.x;

    #pragma unroll
    for (int i = tid; i < SW * SH; i += TS_X * TS_Y) {
        const int r = i / SW, lxx = i % SW;
        const int gx  = reflect(tx0 + lxx - PAD, IMG_W);
        const int gyA = reflect(ty0 + r - PAD, IMG_H);
        const int gyB = reflect(ty0 + HALF_H + r - PAD, IMG_H);
        tile[r][lxx] = __floats2half2_rn(img[gyA * IMG_W + gx], img[gyB * IMG_W + gx]);
    }
    __syncthreads();

    const int lx = threadIdx.x;
    const int wy = ROWS_PER_T * threadIdx.y;   // first output row (tile row offset)

    __half2 buf[132];
    #pragma unroll
    for (int r = 0; r < 10; ++r)
        #pragma unroll
        for (int cc = 0; cc < 7; ++cc)
            buf[r * 7 + cc] = tile[wy + r][lx + cc];

    #pragma unroll
    for (int k = 0; k < PROG.n; ++k) {
        if (PROG.ops[k].k == 0) s2(buf[PROG.ops[k].a], buf[PROG.ops[k].b]);
        else                    buf[PROG.ops[k].b] = buf[PROG.ops[k].a];
    }

    const float mu = c_mean[c], sd = c_std[c];
    const float inv_sd = 1.0f / sd;
    const int gx = tx0 + lx;

    #pragma unroll
    for (int px = 0; px < ROWS_PER_T; ++px) {
        const __half2 med2 = buf[PROG.med[px]];
        const float medA = __low2float(med2);
        const float medB = __high2float(med2);

        float uA = fmaf(medA, sd, mu);
        uA = fminf(fmaxf(uA, 0.0f), 1.0f);
        o[(ty0 + wy + px) * IMG_W + gx] = (uA - mu) * inv_sd;

        float uB = fmaf(medB, sd, mu);
        uB = fminf(fmaxf(uB, 0.0f), 1.0f);
        o[(ty0 + HALF_H + wy + px) * IMG_W + gx] = (uB - mu) * inv_sd;
    }
}

extern "C" void kernel_launch(void* const* d_in, const int* in_sizes, int n_in,
                              void* d_out, int out_size)
{
    const float* image = (const float*)d_in[0];
    const float* mask  = (const float*)d_in[1];
    float* out = (float*)d_out;

    const int img_elems  = in_sizes[0];
    const int mask_elems = in_sizes[1];
    const int planes = img_elems / (IMG_W * IMG_H);

    dim3 block(TS_X, TS_Y);
    dim3 grid(IMG_W / TS_X, IMG_H / TILE_H, planes);
    median7_kernel<<<grid, block>>>(image, out);

    cudaMemcpyAsync(out + img_elems, mask,
                    (size_t)mask_elems * sizeof(float),
                    cudaMemcpyDeviceToDevice, 0);
}

// round 15
// speedup vs baseline: 1.6302x; 1.0464x over previous
#include <cuda_runtime.h>
#include <cuda_fp16.h>
#include <stdint.h>

#define TS_X 32
#define TS_Y 8
#define ROWS_PER_T 4               // output rows per thread (per fp16 lane)
#define HALF_H (TS_Y * ROWS_PER_T) // 32
#define TILE_H (2 * HALF_H)        // 64 output rows per block (2 fp16 lanes)
#define PAD 3
#define SW (TS_X + 2*PAD)          // 38
#define SH (HALF_H + 2*PAD)        // 38
#define IMG_W 512
#define IMG_H 512

__constant__ float c_mean[3] = {0.485f, 0.456f, 0.406f};
__constant__ float c_std[3]  = {0.229f, 0.224f, 0.225f};

// ---------------- compile-time network generation ----------------
// k=0: CE(buf[a],buf[b])   k=1: buf[b]=buf[a]
// k=2: buf[d]=max(buf[a],buf[b])   k=3: buf[d]=min(buf[a],buf[b])
struct Op { unsigned char k, a, b, d; };
struct IL { unsigned char v[44]; int n; };
struct Frag { Op ops[192]; int n; };
struct Prog { Op ops[900]; int n; unsigned char med[4]; };

__host__ __device__ static constexpr IL make_row(int r) {
    IL x{}; for (int c = 0; c < 7; ++c) x.v[x.n++] = (unsigned char)(r * 7 + c);
    return x;
}

__host__ __device__ static constexpr void zipF(Frag& D, const Frag& A, const Frag& B) {
    int i = 0, j = 0;
    while (i < A.n || j < B.n) {
        if (i < A.n) D.ops[D.n++] = A.ops[i++];
        if (j < B.n) D.ops[D.n++] = B.ops[j++];
    }
}

__host__ __device__ static constexpr void appendF(Prog& P, const Frag& F) {
    for (int i = 0; i < F.n; ++i) P.ops[P.n++] = F.ops[i];
}

// Batcher odd-even merge; even/odd sub-merges act on disjoint, already-live
// slots, so zipping them is liveness-neutral ILP (validated R14).
__host__ __device__ static constexpr IL oem(const IL A, const IL B, Frag& P) {
    if (A.n == 0) return B;
    if (B.n == 0) return A;
    IL R{};
    if (A.n == 1 && B.n == 1) {
        P.ops[P.n++] = {0, A.v[0], B.v[0], 0};
        R.v[0] = A.v[0]; R.v[1] = B.v[0]; R.n = 2; return R;
    }
    IL Ae{}, Ao{}, Be{}, Bo{};
    for (int i = 0; i < A.n; ++i) { if (i % 2 == 0) Ae.v[Ae.n++] = A.v[i]; else Ao.v[Ao.n++] = A.v[i]; }
    for (int i = 0; i < B.n; ++i) { if (i % 2 == 0) Be.v[Be.n++] = B.v[i]; else Bo.v[Bo.n++] = B.v[i]; }
    Frag Pe{}, Po{};
    IL E = oem(Ae, Be, Pe);
    IL O = oem(Ao, Bo, Po);
    zipF(P, Pe, Po);
    R.v[R.n++] = E.v[0];
    int i = 1, j = 0;
    while (i < E.n && j < O.n) {
        P.ops[P.n++] = {0, O.v[j], E.v[i], 0};   // min -> O slot, max -> E slot
        R.v[R.n++] = O.v[j]; R.v[R.n++] = E.v[i];
        ++i; ++j;
    }
    while (j < O.n) R.v[R.n++] = O.v[j++];
    while (i < E.n) R.v[R.n++] = E.v[i++];
    return R;
}

__host__ __device__ static constexpr IL sort_gen(const IL A, Frag& P) {
    if (A.n <= 1) return A;
    IL L{}, R{};
    const int m = A.n / 2;
    for (int i = 0; i < m;   ++i) L.v[L.n++] = A.v[i];
    for (int i = m; i < A.n; ++i) R.v[R.n++] = A.v[i];
    Frag Pl{}, Pr{};
    IL Ls = sort_gen(L, Pl), Rs = sort_gen(R, Pr);
    zipF(P, Pl, Pr);
    return oem(Ls, Rs, P);
}

__host__ __device__ static constexpr IL copy_gen(const IL A, int dst0, Frag& P) {
    IL R{};
    for (int i = 0; i < A.n; ++i) {
        P.ops[P.n++] = {1, A.v[i], (unsigned char)(dst0 + i), 0};
        R.v[R.n++] = (unsigned char)(dst0 + i);
    }
    return R;
}

__host__ __device__ static constexpr IL sub(const IL A, int lo, int cnt) {
    IL R{}; for (int i = 0; i < cnt; ++i) R.v[R.n++] = A.v[lo + i]; return R;
}

// Non-destructive rank-8 (1-indexed) of sorted A[0..7] union sorted B[0..6]:
//   result = min over i+j=8 (1<=i<=8) of max(A[i-1], B[j-1]); j=0 term = A[7].
// 7 maxes into scratch s..s+6, then an 7-op min tree; answer lands in s.
__host__ __device__ static constexpr unsigned char sel9_gen(const IL A, const IL B,
                                                            int s, Frag& P) {
    for (int t = 0; t < 7; ++t)
        P.ops[P.n++] = {2, A.v[t], B.v[6 - t], (unsigned char)(s + t)};
    P.ops[P.n++] = {3, (unsigned char)(s + 0), (unsigned char)(s + 1), (unsigned char)(s + 0)};
    P.ops[P.n++] = {3, (unsigned char)(s + 2), (unsigned char)(s + 3), (unsigned char)(s + 2)};
    P.ops[P.n++] = {3, (unsigned char)(s + 4), (unsigned char)(s + 5), (unsigned char)(s + 4)};
    P.ops[P.n++] = {3, A.v[7], (unsigned char)(s + 6), (unsigned char)(s + 6)};
    P.ops[P.n++] = {3, (unsigned char)(s + 0), (unsigned char)(s + 2), (unsigned char)(s + 0)};
    P.ops[P.n++] = {3, (unsigned char)(s + 4), (unsigned char)(s + 6), (unsigned char)(s + 4)};
    P.ops[P.n++] = {3, (unsigned char)(s + 0), (unsigned char)(s + 4), (unsigned char)(s + 0)};
    return (unsigned char)s;
}

// Serial lifetime-disjoint module order (R11/R14), destructive Batcher F
// merges, non-destructive selection for the four G stages (no m-band copies).
__host__ __device__ static constexpr Prog build() {
    Prog P{};
    Frag f{}; IL L3 = sort_gen(make_row(3), f); IL L4 = sort_gen(make_row(4), f);
    IL Bb = oem(L3, L4, f); appendF(P, f);
    Frag g{}; IL L5 = sort_gen(make_row(5), g); IL L6 = sort_gen(make_row(6), g);
    IL Bc = oem(L5, L6, g); appendF(P, g);
    Frag h{}; IL M = oem(Bb, Bc, h); IL Mc = copy_gen(M, 84, h); appendF(P, h);
    // ---- pair 2 (windows rows 2..8 and 3..9) ----
    Frag i1{}; IL L7 = sort_gen(make_row(7), i1); IL c7 = copy_gen(L7, 77, i1);
    IL L8 = sort_gen(make_row(8), i1); IL Bd = oem(L7, L8, i1); appendF(P, i1);
    Frag i2{}; IL F2 = oem(M, Bd, i2); appendF(P, i2);
    IL m2 = sub(F2, 17, 8);             // 0-idx ranks 17..24: only possible medians
    Frag i3a{}, i3b{}, i3{};
    IL L2 = sort_gen(make_row(2), i3a);
    IL L9 = sort_gen(make_row(9), i3b);
    zipF(i3, i3a, i3b); appendF(P, i3);
    Frag i4a{}, i4b{}, i4{};
    P.med[2] = sel9_gen(m2, L2, 112, i4a);   // non-destructive: L2 stays sorted
    P.med[3] = sel9_gen(m2, L9, 119, i4b);
    zipF(i4, i4a, i4b); appendF(P, i4);
    // ---- pair 1 (windows rows 0..6 and 1..7) ----
    Frag j1{}; IL L1 = sort_gen(make_row(1), j1);
    IL Ba = oem(L1, L2, j1); appendF(P, j1);     // destroys L1/L2 (now safe)
    Frag j2{}; IL F1 = oem(Mc, Ba, j2); appendF(P, j2);
    IL m1 = sub(F1, 17, 8);
    Frag j3{}; IL L0 = sort_gen(make_row(0), j3); appendF(P, j3);
    Frag j4a{}, j4b{}, j4{};
    P.med[0] = sel9_gen(m1, L0, 126, j4a);
    P.med[1] = sel9_gen(m1, c7, 133, j4b);
    zipF(j4, j4a, j4b); appendF(P, j4);
    return P;
}

// ---------------- kernel ----------------
__device__ __forceinline__ void s2(__half2& a, __half2& b) {
    __half2 mn = __hmin2(a, b);
    b = __hmax2(a, b);
    a = mn;
}

__device__ __forceinline__ int reflect(int v, int n) {
    v = v < 0 ? -v : v;
    return v >= n ? 2 * (n - 1) - v : v;
}

__global__ __launch_bounds__(TS_X * TS_Y, 4) void median7_kernel(
    const float* __restrict__ in, float* __restrict__ out)
{
    // Compile-time evaluated; all indices are literals after unroll, so the
    // whole network folds to straight-line register code.
    constexpr Prog PROG = build();

    __shared__ __half2 tile[SH][SW];

    const int z = blockIdx.z;
    const int c = z % 3;
    const float* img = in + (size_t)z * (IMG_W * IMG_H);
    float* o = out + (size_t)z * (IMG_W * IMG_H);

    const int tx0 = blockIdx.x * TS_X;
    const int ty0 = blockIdx.y * TILE_H;
    const int tid = threadIdx.y * TS_X + threadIdx.x;

    #pragma unroll
    for (int i = tid; i < SW * SH; i += TS_X * TS_Y) {
        const int r = i / SW, lxx = i % SW;
        const int gx  = reflect(tx0 + lxx - PAD, IMG_W);
        const int gyA = reflect(ty0 + r - PAD, IMG_H);
        const int gyB = reflect(ty0 + HALF_H + r - PAD, IMG_H);
        tile[r][lxx] = __floats2half2_rn(img[gyA * IMG_W + gx], img[gyB * IMG_W + gx]);
    }
    __syncthreads();

    const int lx = threadIdx.x;
    const int wy = ROWS_PER_T * threadIdx.y;   // first output row (tile row offset)

    __half2 buf[140];
    #pragma unroll
    for (int r = 0; r < 10; ++r)
        #pragma unroll
        for (int cc = 0; cc < 7; ++cc)
            buf[r * 7 + cc] = tile[wy + r][lx + cc];

    #pragma unroll
    for (int k = 0; k < PROG.n; ++k) {
        const int kk = PROG.ops[k].k;
        if      (kk == 0) s2(buf[PROG.ops[k].a], buf[PROG.ops[k].b]);
        else if (kk == 1) buf[PROG.ops[k].b] = buf[PROG.ops[k].a];
        else if (kk == 2) buf[PROG.ops[k].d] = __hmax2(buf[PROG.ops[k].a], buf[PROG.ops[k].b]);
        else              buf[PROG.ops[k].d] = __hmin2(buf[PROG.ops[k].a], buf[PROG.ops[k].b]);
    }

    const float mu = c_mean[c], sd = c_std[c];
    const float inv_sd = 1.0f / sd;
    const int gx = tx0 + lx;

    #pragma unroll
    for (int px = 0; px < ROWS_PER_T; ++px) {
        const __half2 med2 = buf[PROG.med[px]];
        const float medA = __low2float(med2);
        const float medB = __high2float(med2);

        const float uA = __saturatef(fmaf(medA, sd, mu));   // FFMA.SAT: free clamp
        o[(ty0 + wy + px) * IMG_W + gx] = (uA - mu) * inv_sd;

        const float uB = __saturatef(fmaf(medB, sd, mu));
        o[(ty0 + HALF_H + wy + px) * IMG_W + gx] = (uB - mu) * inv_sd;
    }
}

extern "C" void kernel_launch(void* const* d_in, const int* in_sizes, int n_in,
                              void* d_out, int out_size)
{
    const float* image = (const float*)d_in[0];
    const float* mask  = (const float*)d_in[1];
    float* out = (float*)d_out;

    const int img_elems  = in_sizes[0];
    const int mask_elems = in_sizes[1];
    const int planes = img_elems / (IMG_W * IMG_H);

    dim3 block(TS_X, TS_Y);
    dim3 grid(IMG_W / TS_X, IMG_H / TILE_H, planes);
    median7_kernel<<<grid, block>>>(image, out);

    cudaMemcpyAsync(out + img_elems, mask,
                    (size_t)mask_elems * sizeof(float),
                    cudaMemcpyDeviceToDevice, 0);
}